// round 1
// baseline (speedup 1.0000x reference)
#include <cuda_runtime.h>
#include <math.h>

// ---------------- problem constants (fixed by dataset) ----------------
#define B_BATCH   2
#define LEN_TOK   5440
#define M_TOK     (B_BATCH * LEN_TOK)   // 10880
#define DMODEL    256
#define NHEAD     8
#define HDIM      32
#define NLVL      4
#define NPT       4
#define DFF       2048

// level geometry (square levels)
__device__ __constant__ int c_lvlW[4]     = {64, 32, 16, 8};
__device__ __constant__ int c_lvlStart[4] = {0, 4096, 5120, 5376};

// ---------------- scratch (static device globals; no allocation) ------
__device__ float g_q   [M_TOK * DMODEL];
__device__ float g_val [M_TOK * DMODEL];
__device__ float g_off [M_TOK * DMODEL];
__device__ float g_attn[M_TOK * 128];
__device__ float g_samp[M_TOK * DMODEL];
__device__ float g_out2[M_TOK * DMODEL];
__device__ float g_x   [M_TOK * DMODEL];
__device__ float g_ffh [M_TOK * DFF];
__device__ float g_ff  [M_TOK * DMODEL];

// ---------------- elementwise add: q = src + pos -----------------------
__global__ void add_kernel(const float* __restrict__ a, const float* __restrict__ b,
                           float* __restrict__ o, int n)
{
    int i = blockIdx.x * blockDim.x + threadIdx.x;
    if (i < n) o[i] = a[i] + b[i];
}

// ---------------- fp32 tiled GEMM: C[M,N] = A[M,K] @ W[K,N] + bias -----
// BM=128, BN=64, BK=16, 256 threads, each thread computes 8x4.
// Requires: M % 128 == 0, N % 64 == 0, K % 16 == 0 (true for all calls here).
template <bool RELU>
__global__ __launch_bounds__(256)
void gemm_kernel(const float* __restrict__ A, const float* __restrict__ W,
                 const float* __restrict__ bias, float* __restrict__ C,
                 int M, int N, int K)
{
    __shared__ float As[16][132];   // padded: conflict-free transposed stores
    __shared__ float Ws[16][64];

    const int t  = threadIdx.x;
    const int m0 = blockIdx.y * 128;
    const int n0 = blockIdx.x * 64;
    const int tx = t & 15;          // n direction (0..15)
    const int ty = t >> 4;          // m direction (0..15)

    // A loads: 128x16 tile, 2 float4 per thread
    const int ar  = t >> 2;         // 0..63
    const int ac4 = (t & 3) * 4;    // 0,4,8,12
    // W loads: 16x64 tile, 1 float4 per thread
    const int wr  = t >> 4;         // 0..15
    const int wc4 = (t & 15) * 4;   // 0..60

    float acc[8][4];
#pragma unroll
    for (int i = 0; i < 8; i++)
#pragma unroll
        for (int j = 0; j < 4; j++) acc[i][j] = 0.0f;

    for (int k0 = 0; k0 < K; k0 += 16) {
        float4 a0 = *(const float4*)&A[(size_t)(m0 + ar)      * K + k0 + ac4];
        float4 a1 = *(const float4*)&A[(size_t)(m0 + ar + 64) * K + k0 + ac4];
        float4 w0 = *(const float4*)&W[(size_t)(k0 + wr) * N + n0 + wc4];

        __syncthreads();
        As[ac4 + 0][ar] = a0.x;  As[ac4 + 1][ar] = a0.y;
        As[ac4 + 2][ar] = a0.z;  As[ac4 + 3][ar] = a0.w;
        As[ac4 + 0][ar + 64] = a1.x;  As[ac4 + 1][ar + 64] = a1.y;
        As[ac4 + 2][ar + 64] = a1.z;  As[ac4 + 3][ar + 64] = a1.w;
        *(float4*)&Ws[wr][wc4] = w0;
        __syncthreads();

#pragma unroll
        for (int kk = 0; kk < 16; kk++) {
            float4 am0 = *(const float4*)&As[kk][ty * 8];
            float4 am1 = *(const float4*)&As[kk][ty * 8 + 4];
            float4 bn  = *(const float4*)&Ws[kk][tx * 4];
            float am[8] = {am0.x, am0.y, am0.z, am0.w, am1.x, am1.y, am1.z, am1.w};
            float bv[4] = {bn.x, bn.y, bn.z, bn.w};
#pragma unroll
            for (int i = 0; i < 8; i++)
#pragma unroll
                for (int j = 0; j < 4; j++)
                    acc[i][j] = fmaf(am[i], bv[j], acc[i][j]);
        }
    }

    float4 bb = *(const float4*)&bias[n0 + tx * 4];
    float bvv[4] = {bb.x, bb.y, bb.z, bb.w};
#pragma unroll
    for (int i = 0; i < 8; i++) {
        int m = m0 + ty * 8 + i;
        float4 o;
        float v0 = acc[i][0] + bvv[0];
        float v1 = acc[i][1] + bvv[1];
        float v2 = acc[i][2] + bvv[2];
        float v3 = acc[i][3] + bvv[3];
        if (RELU) {
            v0 = fmaxf(v0, 0.f); v1 = fmaxf(v1, 0.f);
            v2 = fmaxf(v2, 0.f); v3 = fmaxf(v3, 0.f);
        }
        o.x = v0; o.y = v1; o.z = v2; o.w = v3;
        *(float4*)&C[(size_t)m * N + n0 + tx * 4] = o;
    }
}

// ---------------- deformable sampling + fused softmax ------------------
// grid = M_TOK blocks, 256 threads = 8 warps, warp h handles head h.
// lane d (0..31) owns output channel d of that head.
__global__ __launch_bounds__(256)
void sample_kernel(const float* __restrict__ value,
                   const float* __restrict__ offb,
                   const float* __restrict__ attnb,
                   float* __restrict__ samp)
{
    const int m    = blockIdx.x;
    const int h    = threadIdx.x >> 5;
    const int lane = threadIdx.x & 31;
    const int b    = m / LEN_TOK;
    const int qi   = m - b * LEN_TOK;

    // reference point for this query
    int Wq, idx;
    if      (qi < 4096) { Wq = 64; idx = qi; }
    else if (qi < 5120) { Wq = 32; idx = qi - 4096; }
    else if (qi < 5376) { Wq = 16; idx = qi - 5120; }
    else                { Wq = 8;  idx = qi - 5376; }
    const int   row = idx / Wq;
    const int   col = idx - row * Wq;
    const float rx  = (col + 0.5f) / (float)Wq;
    const float ry  = (row + 0.5f) / (float)Wq;

    // lane i holds offset element i of this head (32 floats: 16 (x,y) pairs)
    const float offv = offb[(size_t)m * 256 + h * 32 + lane];

    // softmax over 16 logits (lane j < 16 holds logit j)
    float logit = (lane < 16) ? attnb[(size_t)m * 128 + h * 16 + lane] : -1e30f;
    float mx = logit;
#pragma unroll
    for (int s = 8; s > 0; s >>= 1) mx = fmaxf(mx, __shfl_xor_sync(0xffffffffu, mx, s));
    float e = (lane < 16) ? expf(logit - mx) : 0.0f;
    float sm = e;
#pragma unroll
    for (int s = 8; s > 0; s >>= 1) sm += __shfl_xor_sync(0xffffffffu, sm, s);
    float prob = e / sm;   // valid on lanes 0..15 (only those are shuffled from)

    float acc = 0.0f;
#pragma unroll
    for (int l = 0; l < 4; l++) {
        const int   Wl  = c_lvlW[l];
        const float Wf  = (float)Wl;
        const float inv = 1.0f / Wf;
        const float* vbase = value + ((size_t)b * LEN_TOK + c_lvlStart[l]) * 256 + h * 32 + lane;
#pragma unroll
        for (int p = 0; p < 4; p++) {
            const int j = l * 4 + p;
            const float a  = __shfl_sync(0xffffffffu, prob, j);
            const float ox = __shfl_sync(0xffffffffu, offv, 2 * j);
            const float oy = __shfl_sync(0xffffffffu, offv, 2 * j + 1);
            const float x = (rx + ox * inv) * Wf - 0.5f;
            const float y = (ry + oy * inv) * Wf - 0.5f;
            const float x0f = floorf(x), y0f = floorf(y);
            const float dx = x - x0f,  dy = y - y0f;
            const int x0 = (int)x0f, y0 = (int)y0f;
            const bool vx0 = (x0 >= 0)     & (x0 < Wl);
            const bool vx1 = (x0 + 1 >= 0) & (x0 + 1 < Wl);
            const bool vy0 = (y0 >= 0)     & (y0 < Wl);
            const bool vy1 = (y0 + 1 >= 0) & (y0 + 1 < Wl);
            const float w00 = (1.f - dx) * (1.f - dy) * a;
            const float w10 = dx * (1.f - dy) * a;
            const float w01 = (1.f - dx) * dy * a;
            const float w11 = dx * dy * a;
            if (vx0 & vy0) acc = fmaf(w00, vbase[(size_t)(y0 * Wl + x0) * 256], acc);
            if (vx1 & vy0) acc = fmaf(w10, vbase[(size_t)(y0 * Wl + x0 + 1) * 256], acc);
            if (vx0 & vy1) acc = fmaf(w01, vbase[(size_t)((y0 + 1) * Wl + x0) * 256], acc);
            if (vx1 & vy1) acc = fmaf(w11, vbase[(size_t)((y0 + 1) * Wl + x0 + 1) * 256], acc);
        }
    }
    samp[(size_t)m * 256 + h * 32 + lane] = acc;
}

// ---------------- fused residual-add + LayerNorm ------------------------
// grid = M_TOK, 256 threads (one per channel)
__global__ __launch_bounds__(256)
void add_ln_kernel(const float* __restrict__ A, const float* __restrict__ Bv,
                   const float* __restrict__ gamma, const float* __restrict__ beta,
                   float* __restrict__ out)
{
    const int m = blockIdx.x;
    const int t = threadIdx.x;
    const float v = A[(size_t)m * 256 + t] + Bv[(size_t)m * 256 + t];

    float s = v, q2 = v * v;
#pragma unroll
    for (int sft = 16; sft > 0; sft >>= 1) {
        s  += __shfl_xor_sync(0xffffffffu, s,  sft);
        q2 += __shfl_xor_sync(0xffffffffu, q2, sft);
    }
    __shared__ float ws[8], wq[8], mv[2];
    const int wid = t >> 5, lane = t & 31;
    if (lane == 0) { ws[wid] = s; wq[wid] = q2; }
    __syncthreads();
    if (t == 0) {
        float ts = 0.f, tq = 0.f;
#pragma unroll
        for (int i = 0; i < 8; i++) { ts += ws[i]; tq += wq[i]; }
        const float mean = ts * (1.0f / 256.0f);
        const float var  = tq * (1.0f / 256.0f) - mean * mean;
        mv[0] = mean;
        mv[1] = rsqrtf(var + 1e-5f);
    }
    __syncthreads();
    out[(size_t)m * 256 + t] = (v - mv[0]) * mv[1] * gamma[t] + beta[t];
}

// ---------------- launch -------------------------------------------------
static inline float* sym(const void* s)
{
    void* p = nullptr;
    cudaGetSymbolAddress(&p, s);
    return (float*)p;
}

extern "C" void kernel_launch(void* const* d_in, const int* in_sizes, int n_in,
                              void* d_out, int out_size)
{
    const float* src     = (const float*)d_in[0];
    const float* pos     = (const float*)d_in[1];
    // d_in[2] spatial_shapes, d_in[3] level_start_index: constants, unused
    const float* w_value = (const float*)d_in[4];
    const float* b_value = (const float*)d_in[5];
    const float* w_off   = (const float*)d_in[6];
    const float* b_off   = (const float*)d_in[7];
    const float* w_attn  = (const float*)d_in[8];
    const float* b_attn  = (const float*)d_in[9];
    const float* w_out   = (const float*)d_in[10];
    const float* b_out   = (const float*)d_in[11];
    const float* w1      = (const float*)d_in[12];
    const float* b1      = (const float*)d_in[13];
    const float* w2      = (const float*)d_in[14];
    const float* b2      = (const float*)d_in[15];
    const float* g1      = (const float*)d_in[16];
    const float* be1     = (const float*)d_in[17];
    const float* g2      = (const float*)d_in[18];
    const float* be2     = (const float*)d_in[19];
    float* out = (float*)d_out;

    float* q    = sym(g_q);
    float* val  = sym(g_val);
    float* off  = sym(g_off);
    float* attn = sym(g_attn);
    float* samp = sym(g_samp);
    float* out2 = sym(g_out2);
    float* x    = sym(g_x);
    float* ffh  = sym(g_ffh);
    float* ff   = sym(g_ff);

    const int n_qd = M_TOK * DMODEL;

    // q = src + pos
    add_kernel<<<(n_qd + 255) / 256, 256>>>(src, pos, q, n_qd);

    // projections
    dim3 gv(DMODEL / 64, M_TOK / 128);
    gemm_kernel<false><<<gv, 256>>>(src, w_value, b_value, val, M_TOK, DMODEL, DMODEL);
    gemm_kernel<false><<<gv, 256>>>(q,   w_off,   b_off,   off, M_TOK, DMODEL, DMODEL);
    dim3 ga(128 / 64, M_TOK / 128);
    gemm_kernel<false><<<ga, 256>>>(q,   w_attn,  b_attn,  attn, M_TOK, 128, DMODEL);

    // deformable sampling (softmax fused)
    sample_kernel<<<M_TOK, 256>>>(val, off, attn, samp);

    // output projection
    gemm_kernel<false><<<gv, 256>>>(samp, w_out, b_out, out2, M_TOK, DMODEL, DMODEL);

    // x = LN(src + out2)
    add_ln_kernel<<<M_TOK, 256>>>(src, out2, g1, be1, x);

    // FFN
    dim3 gf1(DFF / 64, M_TOK / 128);
    gemm_kernel<true ><<<gf1, 256>>>(x,   w1, b1, ffh, M_TOK, DFF, DMODEL);
    gemm_kernel<false><<<gv,  256>>>(ffh, w2, b2, ff,  M_TOK, DMODEL, DFF);

    // out = LN(x + ff)
    add_ln_kernel<<<M_TOK, 256>>>(x, ff, g2, be2, out);
}

// round 3
// speedup vs baseline: 2.2428x; 2.2428x over previous
#include <cuda_runtime.h>
#include <cstdint>
#include <math.h>

// ---------------- problem constants (fixed by dataset) ----------------
#define B_BATCH   2
#define LEN_TOK   5440
#define M_TOK     (B_BATCH * LEN_TOK)   // 10880
#define DMODEL    256
#define NHEAD     8
#define NLVL      4
#define NPT       4
#define DFF       2048

__device__ __constant__ int c_lvlW[4]     = {64, 32, 16, 8};
__device__ __constant__ int c_lvlStart[4] = {0, 4096, 5120, 5376};

// ---------------- scratch (static device globals; no allocation) ------
__device__ float g_q   [M_TOK * DMODEL];
__device__ float g_val [M_TOK * DMODEL];
__device__ float g_off [M_TOK * DMODEL];
__device__ float g_attn[M_TOK * 128];
__device__ float g_samp[M_TOK * DMODEL];
__device__ float g_out2[M_TOK * DMODEL];
__device__ float g_x   [M_TOK * DMODEL];
__device__ float g_ffh [M_TOK * DFF];
__device__ float g_part[4 * M_TOK * DMODEL];   // split-K partials for FFN2
// transposed weights [N, K]
__device__ float g_wvT   [256 * 256];
__device__ float g_woffT [256 * 256];
__device__ float g_wattnT[128 * 256];
__device__ float g_woutT [256 * 256];
__device__ float g_w1T   [2048 * 256];
__device__ float g_w2T   [256 * 2048];

// ---------------- helpers ------------------------------------------------
__device__ __forceinline__ uint32_t f2tf32(float f) {
    uint32_t u;
    asm("cvt.rna.tf32.f32 %0, %1;" : "=r"(u) : "f"(f));
    return u;
}
__device__ __forceinline__ void mma_tf32(float* c, const uint32_t* a, const uint32_t* b) {
    asm volatile(
        "mma.sync.aligned.m16n8k8.row.col.f32.tf32.tf32.f32 "
        "{%0,%1,%2,%3}, {%4,%5,%6,%7}, {%8,%9}, {%0,%1,%2,%3};\n"
        : "+f"(c[0]), "+f"(c[1]), "+f"(c[2]), "+f"(c[3])
        : "r"(a[0]), "r"(a[1]), "r"(a[2]), "r"(a[3]), "r"(b[0]), "r"(b[1]));
}

// ---------------- elementwise add (float4) -------------------------------
__global__ void add_kernel(const float4* __restrict__ a, const float4* __restrict__ b,
                           float4* __restrict__ o, int n4)
{
    int i = blockIdx.x * blockDim.x + threadIdx.x;
    if (i < n4) {
        float4 x = a[i], y = b[i];
        o[i] = make_float4(x.x + y.x, x.y + y.y, x.z + y.z, x.w + y.w);
    }
}

// ---------------- weight transpose: out[C,R] = in[R,C]^T ----------------
__global__ __launch_bounds__(256)
void transpose_kernel(const float* __restrict__ in, float* __restrict__ out, int R, int C)
{
    __shared__ float tile[32][33];
    const int c0 = blockIdx.x * 32, r0 = blockIdx.y * 32;
    const int x = threadIdx.x, y = threadIdx.y;  // block (32, 8)
#pragma unroll
    for (int i = 0; i < 32; i += 8)
        tile[y + i][x] = in[(size_t)(r0 + y + i) * C + c0 + x];
    __syncthreads();
#pragma unroll
    for (int i = 0; i < 32; i += 8)
        out[(size_t)(c0 + y + i) * R + r0 + x] = tile[x][y + i];
}

// ---------------- tf32 mma.sync GEMM -------------------------------------
// C[M,N] = A[M,kLen] @ BT[N,kLen]^T (+ bias, + relu per MODE)
// CTA tile 128x128, BK=32, 256 threads = 8 warps (2m x 4n), warp tile 64x32.
// Split-K via blockIdx.z: slice z uses A/BT columns [z*kLen, (z+1)*kLen),
// writes C + z*cSlice. Requires M%128==0, N%128==0, kLen%32==0.
// MODE: 0 = +bias, 1 = +bias+relu, 2 = raw partial (no bias)
#define LDP 36   // padded row length (floats) in smem: conflict-free frags
template <int MODE>
__global__ __launch_bounds__(256, 2)
void gemm_mma(const float* __restrict__ A, int lda,
              const float* __restrict__ BT, int ldb,
              float* __restrict__ C, int ldc, size_t cSlice,
              const float* __restrict__ bias, int kLen)
{
    __shared__ float sm[2 * 128 * LDP];
    float* As = sm;
    float* Bs = sm + 128 * LDP;

    const int t    = threadIdx.x;
    const int warp = t >> 5;
    const int lane = t & 31;
    const int wm   = warp >> 2;        // 0..1
    const int wn   = warp & 3;         // 0..3
    const int g    = lane >> 2;        // 0..7
    const int tq   = lane & 3;         // 0..3
    const int m0   = blockIdx.y * 128;
    const int n0   = blockIdx.x * 128;

    const size_t koff = (size_t)blockIdx.z * kLen;
    A  += koff;
    BT += koff;
    C  += (size_t)blockIdx.z * cSlice;

    // per-thread staging geometry: 4 float4 per operand tile
    int rowi[4], c4i[4];
#pragma unroll
    for (int i = 0; i < 4; i++) {
        const int f = t + i * 256;
        rowi[i] = f >> 3;        // 0..127
        c4i[i]  = (f & 7) * 4;   // float col {0,4,...,28}
    }

    float acc[4][4][4];
#pragma unroll
    for (int a_ = 0; a_ < 4; a_++)
#pragma unroll
        for (int b_ = 0; b_ < 4; b_++)
#pragma unroll
            for (int c_ = 0; c_ < 4; c_++) acc[a_][b_][c_] = 0.f;

    const int KT = kLen >> 5;
    float4 ra[4], rb[4];

    // prefetch tile 0
#pragma unroll
    for (int i = 0; i < 4; i++) {
        ra[i] = *(const float4*)&A [(size_t)(m0 + rowi[i]) * lda + c4i[i]];
        rb[i] = *(const float4*)&BT[(size_t)(n0 + rowi[i]) * ldb + c4i[i]];
    }

    for (int kt = 0; kt < KT; kt++) {
        if (kt > 0) __syncthreads();   // previous compute done before overwrite

        // STS (convert to tf32)
#pragma unroll
        for (int i = 0; i < 4; i++) {
            uint4 ua, ub;
            ua.x = f2tf32(ra[i].x); ua.y = f2tf32(ra[i].y);
            ua.z = f2tf32(ra[i].z); ua.w = f2tf32(ra[i].w);
            ub.x = f2tf32(rb[i].x); ub.y = f2tf32(rb[i].y);
            ub.z = f2tf32(rb[i].z); ub.w = f2tf32(rb[i].w);
            *(uint4*)&As[rowi[i] * LDP + c4i[i]] = ua;
            *(uint4*)&Bs[rowi[i] * LDP + c4i[i]] = ub;
        }
        __syncthreads();

        // prefetch next tile (overlaps mma phase)
        if (kt + 1 < KT) {
            const int kb = (kt + 1) * 32;
#pragma unroll
            for (int i = 0; i < 4; i++) {
                ra[i] = *(const float4*)&A [(size_t)(m0 + rowi[i]) * lda + kb + c4i[i]];
                rb[i] = *(const float4*)&BT[(size_t)(n0 + rowi[i]) * ldb + kb + c4i[i]];
            }
        }

        // compute: 4 k-steps of k=8
#pragma unroll
        for (int kq = 0; kq < 4; kq++) {
            const int col = kq * 8 + tq;
            uint32_t bf[4][2];
#pragma unroll
            for (int nt = 0; nt < 4; nt++) {
                const int rn = wn * 32 + nt * 8 + g;
                bf[nt][0] = __float_as_uint(Bs[rn * LDP + col]);
                bf[nt][1] = __float_as_uint(Bs[rn * LDP + col + 4]);
            }
#pragma unroll
            for (int mt = 0; mt < 4; mt++) {
                const int rm = wm * 64 + mt * 16 + g;
                uint32_t af[4];
                af[0] = __float_as_uint(As[rm * LDP + col]);
                af[1] = __float_as_uint(As[(rm + 8) * LDP + col]);
                af[2] = __float_as_uint(As[rm * LDP + col + 4]);
                af[3] = __float_as_uint(As[(rm + 8) * LDP + col + 4]);
#pragma unroll
                for (int nt = 0; nt < 4; nt++)
                    mma_tf32(acc[mt][nt], af, bf[nt]);
            }
        }
    }

    // epilogue
#pragma unroll
    for (int mt = 0; mt < 4; mt++) {
        const int row = m0 + wm * 64 + mt * 16 + g;
#pragma unroll
        for (int nt = 0; nt < 4; nt++) {
            const int col = n0 + wn * 32 + nt * 8 + tq * 2;
            float bx = 0.f, by = 0.f;
            if (MODE < 2) { float2 bb = *(const float2*)&bias[col]; bx = bb.x; by = bb.y; }
            float v0 = acc[mt][nt][0] + bx;
            float v1 = acc[mt][nt][1] + by;
            float v2 = acc[mt][nt][2] + bx;
            float v3 = acc[mt][nt][3] + by;
            if (MODE == 1) {
                v0 = fmaxf(v0, 0.f); v1 = fmaxf(v1, 0.f);
                v2 = fmaxf(v2, 0.f); v3 = fmaxf(v3, 0.f);
            }
            *(float2*)&C[(size_t)row * ldc + col]       = make_float2(v0, v1);
            *(float2*)&C[(size_t)(row + 8) * ldc + col] = make_float2(v2, v3);
        }
    }
}

// ---------------- deformable sampling + fused softmax ------------------
__global__ __launch_bounds__(256)
void sample_kernel(const float* __restrict__ value,
                   const float* __restrict__ offb,
                   const float* __restrict__ attnb,
                   float* __restrict__ samp)
{
    const int m    = blockIdx.x;
    const int h    = threadIdx.x >> 5;
    const int lane = threadIdx.x & 31;
    const int b    = m / LEN_TOK;
    const int qi   = m - b * LEN_TOK;

    int Wq, idx;
    if      (qi < 4096) { Wq = 64; idx = qi; }
    else if (qi < 5120) { Wq = 32; idx = qi - 4096; }
    else if (qi < 5376) { Wq = 16; idx = qi - 5120; }
    else                { Wq = 8;  idx = qi - 5376; }
    const int   row = idx / Wq;
    const int   col = idx - row * Wq;
    const float rx  = (col + 0.5f) / (float)Wq;
    const float ry  = (row + 0.5f) / (float)Wq;

    const float offv = offb[(size_t)m * 256 + h * 32 + lane];

    float logit = (lane < 16) ? attnb[(size_t)m * 128 + h * 16 + lane] : -1e30f;
    float mx = logit;
#pragma unroll
    for (int s = 8; s > 0; s >>= 1) mx = fmaxf(mx, __shfl_xor_sync(0xffffffffu, mx, s));
    float e = (lane < 16) ? expf(logit - mx) : 0.0f;
    float sm = e;
#pragma unroll
    for (int s = 8; s > 0; s >>= 1) sm += __shfl_xor_sync(0xffffffffu, sm, s);
    float prob = e / sm;

    float acc = 0.0f;
#pragma unroll
    for (int l = 0; l < 4; l++) {
        const int   Wl  = c_lvlW[l];
        const float Wf  = (float)Wl;
        const float inv = 1.0f / Wf;
        const float* vbase = value + ((size_t)b * LEN_TOK + c_lvlStart[l]) * 256 + h * 32 + lane;
#pragma unroll
        for (int p = 0; p < 4; p++) {
            const int j = l * 4 + p;
            const float a  = __shfl_sync(0xffffffffu, prob, j);
            const float ox = __shfl_sync(0xffffffffu, offv, 2 * j);
            const float oy = __shfl_sync(0xffffffffu, offv, 2 * j + 1);
            const float x = (rx + ox * inv) * Wf - 0.5f;
            const float y = (ry + oy * inv) * Wf - 0.5f;
            const float x0f = floorf(x), y0f = floorf(y);
            const float dx = x - x0f,  dy = y - y0f;
            const int x0 = (int)x0f, y0 = (int)y0f;
            const bool vx0 = (x0 >= 0)     & (x0 < Wl);
            const bool vx1 = (x0 + 1 >= 0) & (x0 + 1 < Wl);
            const bool vy0 = (y0 >= 0)     & (y0 < Wl);
            const bool vy1 = (y0 + 1 >= 0) & (y0 + 1 < Wl);
            const float w00 = (1.f - dx) * (1.f - dy) * a;
            const float w10 = dx * (1.f - dy) * a;
            const float w01 = (1.f - dx) * dy * a;
            const float w11 = dx * dy * a;
            if (vx0 & vy0) acc = fmaf(w00, vbase[(size_t)(y0 * Wl + x0) * 256], acc);
            if (vx1 & vy0) acc = fmaf(w10, vbase[(size_t)(y0 * Wl + x0 + 1) * 256], acc);
            if (vx0 & vy1) acc = fmaf(w01, vbase[(size_t)((y0 + 1) * Wl + x0) * 256], acc);
            if (vx1 & vy1) acc = fmaf(w11, vbase[(size_t)((y0 + 1) * Wl + x0 + 1) * 256], acc);
        }
    }
    samp[(size_t)m * 256 + h * 32 + lane] = acc;
}

// ---------------- fused residual-add + LayerNorm ------------------------
__global__ __launch_bounds__(256)
void add_ln_kernel(const float* __restrict__ A, const float* __restrict__ Bv,
                   const float* __restrict__ gamma, const float* __restrict__ beta,
                   float* __restrict__ out)
{
    const int m = blockIdx.x;
    const int t = threadIdx.x;
    const float v = A[(size_t)m * 256 + t] + Bv[(size_t)m * 256 + t];

    float s = v, q2 = v * v;
#pragma unroll
    for (int sft = 16; sft > 0; sft >>= 1) {
        s  += __shfl_xor_sync(0xffffffffu, s,  sft);
        q2 += __shfl_xor_sync(0xffffffffu, q2, sft);
    }
    __shared__ float ws[8], wq[8], mv[2];
    const int wid = t >> 5, lane = t & 31;
    if (lane == 0) { ws[wid] = s; wq[wid] = q2; }
    __syncthreads();
    if (t == 0) {
        float ts = 0.f, tq_ = 0.f;
#pragma unroll
        for (int i = 0; i < 8; i++) { ts += ws[i]; tq_ += wq[i]; }
        const float mean = ts * (1.0f / 256.0f);
        const float var  = tq_ * (1.0f / 256.0f) - mean * mean;
        mv[0] = mean;
        mv[1] = rsqrtf(var + 1e-5f);
    }
    __syncthreads();
    out[(size_t)m * 256 + t] = (v - mv[0]) * mv[1] * gamma[t] + beta[t];
}

// ---- fused: combine 4 split-K partials + bias + residual + LayerNorm ---
__global__ __launch_bounds__(256)
void add4_ln_kernel(const float* __restrict__ X, const float* __restrict__ P,
                    const float* __restrict__ bias,
                    const float* __restrict__ gamma, const float* __restrict__ beta,
                    float* __restrict__ out)
{
    const int m = blockIdx.x;
    const int t = threadIdx.x;
    const size_t i = (size_t)m * 256 + t;
    const size_t sl = (size_t)M_TOK * 256;
    const float v = X[i] + P[i] + P[i + sl] + P[i + 2 * sl] + P[i + 3 * sl] + bias[t];

    float s = v, q2 = v * v;
#pragma unroll
    for (int sft = 16; sft > 0; sft >>= 1) {
        s  += __shfl_xor_sync(0xffffffffu, s,  sft);
        q2 += __shfl_xor_sync(0xffffffffu, q2, sft);
    }
    __shared__ float ws[8], wq[8], mv[2];
    const int wid = t >> 5, lane = t & 31;
    if (lane == 0) { ws[wid] = s; wq[wid] = q2; }
    __syncthreads();
    if (t == 0) {
        float ts = 0.f, tq_ = 0.f;
#pragma unroll
        for (int ii = 0; ii < 8; ii++) { ts += ws[ii]; tq_ += wq[ii]; }
        const float mean = ts * (1.0f / 256.0f);
        const float var  = tq_ * (1.0f / 256.0f) - mean * mean;
        mv[0] = mean;
        mv[1] = rsqrtf(var + 1e-5f);
    }
    __syncthreads();
    out[i] = (v - mv[0]) * mv[1] * gamma[t] + beta[t];
}

// ---------------- launch -------------------------------------------------
static inline float* sym(const void* s)
{
    void* p = nullptr;
    cudaGetSymbolAddress(&p, s);
    return (float*)p;
}

extern "C" void kernel_launch(void* const* d_in, const int* in_sizes, int n_in,
                              void* d_out, int out_size)
{
    const float* src     = (const float*)d_in[0];
    const float* pos     = (const float*)d_in[1];
    const float* w_value = (const float*)d_in[4];
    const float* b_value = (const float*)d_in[5];
    const float* w_off   = (const float*)d_in[6];
    const float* b_off   = (const float*)d_in[7];
    const float* w_attn  = (const float*)d_in[8];
    const float* b_attn  = (const float*)d_in[9];
    const float* w_out   = (const float*)d_in[10];
    const float* b_out   = (const float*)d_in[11];
    const float* w1      = (const float*)d_in[12];
    const float* b1      = (const float*)d_in[13];
    const float* w2      = (const float*)d_in[14];
    const float* b2      = (const float*)d_in[15];
    const float* g1      = (const float*)d_in[16];
    const float* be1     = (const float*)d_in[17];
    const float* g2      = (const float*)d_in[18];
    const float* be2     = (const float*)d_in[19];
    float* out = (float*)d_out;

    float* q    = sym(g_q);
    float* val  = sym(g_val);
    float* off  = sym(g_off);
    float* attn = sym(g_attn);
    float* samp = sym(g_samp);
    float* out2 = sym(g_out2);
    float* x    = sym(g_x);
    float* ffh  = sym(g_ffh);
    float* part = sym(g_part);
    float* wvT    = sym(g_wvT);
    float* woffT  = sym(g_woffT);
    float* wattnT = sym(g_wattnT);
    float* woutT  = sym(g_woutT);
    float* w1T    = sym(g_w1T);
    float* w2T    = sym(g_w2T);

    const int n_qd = M_TOK * DMODEL;
    dim3 tb(32, 8);

    // q = src + pos
    add_kernel<<<(n_qd / 4 + 255) / 256, 256>>>((const float4*)src, (const float4*)pos,
                                                (float4*)q, n_qd / 4);

    // weight transposes: WT[N,K] = W[K,N]^T
    transpose_kernel<<<dim3(8, 8),   tb>>>(w_value, wvT,    256,  256);
    transpose_kernel<<<dim3(8, 8),   tb>>>(w_off,   woffT,  256,  256);
    transpose_kernel<<<dim3(4, 8),   tb>>>(w_attn,  wattnT, 256,  128);
    transpose_kernel<<<dim3(8, 8),   tb>>>(w_out,   woutT,  256,  256);
    transpose_kernel<<<dim3(64, 8),  tb>>>(w1,      w1T,    256,  2048);
    transpose_kernel<<<dim3(8, 64),  tb>>>(w2,      w2T,    2048, 256);

    // projections (tf32 mma.sync)
    dim3 gv(2, M_TOK / 128, 1);
    gemm_mma<0><<<gv, 256>>>(src, 256, wvT,    256, val,  256, 0, b_value, 256);
    gemm_mma<0><<<gv, 256>>>(q,   256, woffT,  256, off,  256, 0, b_off,   256);
    dim3 ga(1, M_TOK / 128, 1);
    gemm_mma<0><<<ga, 256>>>(q,   256, wattnT, 256, attn, 128, 0, b_attn,  256);

    // deformable sampling (softmax fused)
    sample_kernel<<<M_TOK, 256>>>(val, off, attn, samp);

    // output projection
    gemm_mma<0><<<gv, 256>>>(samp, 256, woutT, 256, out2, 256, 0, b_out, 256);

    // x = LN(src + out2)
    add_ln_kernel<<<M_TOK, 256>>>(src, out2, g1, be1, x);

    // FFN1: relu(x @ w1 + b1)
    dim3 gf1(DFF / 128, M_TOK / 128, 1);
    gemm_mma<1><<<gf1, 256>>>(x, 256, w1T, 256, ffh, DFF, 0, b1, 256);

    // FFN2: split-K=4 partials (kLen=512 each)
    dim3 gf2(2, M_TOK / 128, 4);
    gemm_mma<2><<<gf2, 256>>>(ffh, DFF, w2T, DFF, part, 256,
                              (size_t)M_TOK * 256, nullptr, 512);

    // out = LN(x + sum(parts) + b2)
    add4_ln_kernel<<<M_TOK, 256>>>(x, part, b2, g2, be2, out);
}

// round 4
// speedup vs baseline: 3.5091x; 1.5646x over previous
#include <cuda_runtime.h>
#include <cuda_fp16.h>
#include <cstdint>
#include <math.h>

// ---------------- problem constants (fixed by dataset) ----------------
#define B_BATCH   2
#define LEN_TOK   5440
#define M_TOK     (B_BATCH * LEN_TOK)   // 10880
#define DMODEL    256
#define NHEAD     8
#define NLVL      4
#define NPT       4
#define DFF       2048

__device__ __constant__ int c_lvlW[4]     = {64, 32, 16, 8};
__device__ __constant__ int c_lvlStart[4] = {0, 4096, 5120, 5376};

// ---------------- scratch (static device globals; no allocation) ------
__device__ float  g_val [M_TOK * DMODEL];
__device__ float  g_off [M_TOK * DMODEL];
__device__ float  g_attn[M_TOK * 128];
__device__ float  g_out2[M_TOK * DMODEL];
__device__ float  g_x   [M_TOK * DMODEL];
__device__ float  g_part[4 * M_TOK * DMODEL];   // split-K partials for FFN2
__device__ __half g_srch[M_TOK * DMODEL];
__device__ __half g_qh  [M_TOK * DMODEL];
__device__ __half g_samph[M_TOK * DMODEL];
__device__ __half g_xh  [M_TOK * DMODEL];
__device__ __half g_ffhh[M_TOK * DFF];
// transposed fp16 weights [N, K]
__device__ __half g_wvT   [256 * 256];
__device__ __half g_woffT [256 * 256];
__device__ __half g_wattnT[128 * 256];
__device__ __half g_woutT [256 * 256];
__device__ __half g_w1T   [2048 * 256];
__device__ __half g_w2T   [256 * 2048];

// ---------------- mma / ldmatrix helpers ---------------------------------
__device__ __forceinline__ void mma_f16(float* c, const uint32_t* a, const uint32_t* b) {
    asm volatile(
        "mma.sync.aligned.m16n8k16.row.col.f32.f16.f16.f32 "
        "{%0,%1,%2,%3}, {%4,%5,%6,%7}, {%8,%9}, {%0,%1,%2,%3};\n"
        : "+f"(c[0]), "+f"(c[1]), "+f"(c[2]), "+f"(c[3])
        : "r"(a[0]), "r"(a[1]), "r"(a[2]), "r"(a[3]), "r"(b[0]), "r"(b[1]));
}
__device__ __forceinline__ void ldsm_x4(uint32_t* r, uint32_t addr) {
    asm volatile("ldmatrix.sync.aligned.m8n8.x4.shared.b16 {%0,%1,%2,%3}, [%4];"
                 : "=r"(r[0]), "=r"(r[1]), "=r"(r[2]), "=r"(r[3]) : "r"(addr));
}
__device__ __forceinline__ void ldsm_x2(uint32_t* r, uint32_t addr) {
    asm volatile("ldmatrix.sync.aligned.m8n8.x2.shared.b16 {%0,%1}, [%2];"
                 : "=r"(r[0]), "=r"(r[1]) : "r"(addr));
}

// ---------------- q = src + pos (fp16 copies of both) --------------------
__global__ void addcvt_kernel(const float4* __restrict__ src, const float4* __restrict__ pos,
                              __half2* __restrict__ qh, __half2* __restrict__ srch, int n4)
{
    int i = blockIdx.x * blockDim.x + threadIdx.x;
    if (i < n4) {
        float4 s = src[i], p = pos[i];
        srch[2 * i]     = __floats2half2_rn(s.x, s.y);
        srch[2 * i + 1] = __floats2half2_rn(s.z, s.w);
        qh[2 * i]       = __floats2half2_rn(s.x + p.x, s.y + p.y);
        qh[2 * i + 1]   = __floats2half2_rn(s.z + p.z, s.w + p.w);
    }
}

// ---------------- all 6 weight transposes (fp32 [K,N] -> fp16 [N,K]) ----
__global__ __launch_bounds__(256)
void transpose_all(const float* __restrict__ wv, const float* __restrict__ woff,
                   const float* __restrict__ wattn, const float* __restrict__ wout,
                   const float* __restrict__ w1, const float* __restrict__ w2,
                   __half* __restrict__ wvT, __half* __restrict__ woffT,
                   __half* __restrict__ wattnT, __half* __restrict__ woutT,
                   __half* __restrict__ w1T, __half* __restrict__ w2T)
{
    const int bid = blockIdx.x;
    const float* in; __half* out; int R, C, tix;
    if      (bid < 64)  { in = wv;    out = wvT;    R = 256;  C = 256;  tix = bid; }
    else if (bid < 128) { in = woff;  out = woffT;  R = 256;  C = 256;  tix = bid - 64; }
    else if (bid < 160) { in = wattn; out = wattnT; R = 256;  C = 128;  tix = bid - 128; }
    else if (bid < 224) { in = wout;  out = woutT;  R = 256;  C = 256;  tix = bid - 160; }
    else if (bid < 736) { in = w1;    out = w1T;    R = 256;  C = 2048; tix = bid - 224; }
    else                { in = w2;    out = w2T;    R = 2048; C = 256;  tix = bid - 736; }
    const int tilesX = C / 32;
    const int c0 = (tix % tilesX) * 32, r0 = (tix / tilesX) * 32;

    __shared__ float tile[32][33];
    const int x = threadIdx.x, y = threadIdx.y;   // block (32, 8)
#pragma unroll
    for (int i = 0; i < 32; i += 8)
        tile[y + i][x] = in[(size_t)(r0 + y + i) * C + c0 + x];
    __syncthreads();
#pragma unroll
    for (int i = 0; i < 32; i += 8)
        out[(size_t)(c0 + y + i) * R + r0 + x] = __float2half_rn(tile[x][y + i]);
}

// ---------------- fp16 mma.sync GEMM -------------------------------------
// C[M,N] = A[M,kLen] @ BT[N,kLen]^T (+ bias, + relu per MODE)
// CTA 128x128, BK=32, 256 thr = 8 warps (2m x 4n), warp tile 64x32.
// Double-buffered smem (pad 40 halves/row), ldmatrix fragments.
// Split-K via blockIdx.z. MODE: 0 +bias, 1 +bias+relu, 2 raw partial.
#define LDH      40
#define SMH_OP   (128 * LDH)            // halves per operand buffer
#define OPBYTES  (SMH_OP * 2)           // 10240
#define BUFBYTES (2 * OPBYTES)          // 20480

template <int MODE, typename OutT>
__global__ __launch_bounds__(256, 2)
void gemm_mma(const __half* __restrict__ A, int lda,
              const __half* __restrict__ BT, int ldb,
              OutT* __restrict__ C, int ldc, size_t cSlice,
              const float* __restrict__ bias, int kLen)
{
    __shared__ __align__(16) __half sm[2 * 2 * SMH_OP];

    const int t    = threadIdx.x;
    const int warp = t >> 5;
    const int lane = t & 31;
    const int wm   = warp >> 2;      // 0..1
    const int wn   = warp & 3;       // 0..3
    const int g    = lane >> 2;      // 0..7
    const int tq   = lane & 3;       // 0..3
    const int m0 = blockIdx.y * 128;
    const int n0 = blockIdx.x * 128;

    A  += (size_t)blockIdx.z * kLen;
    BT += (size_t)blockIdx.z * kLen;
    C  += (size_t)blockIdx.z * cSlice;

    const uint32_t sbase = (uint32_t)__cvta_generic_to_shared(sm);

    // staging geometry: 2 chunks of 8 halves per operand per thread
    int rowi[2], cci[2];
#pragma unroll
    for (int i = 0; i < 2; i++) {
        const int f = t + i * 256;
        rowi[i] = f >> 2;             // 0..127
        cci[i]  = (f & 3) * 8;        // 0,8,16,24 (halves)
    }
    // ldmatrix lane geometry
    const int rA = ((lane >> 3) & 1) * 8 + (lane & 7);
    const int cA = (lane >> 4) * 8;
    const int rB = lane & 7;
    const int cB = ((lane >> 3) & 1) * 8;

    float acc[4][4][4];
#pragma unroll
    for (int a_ = 0; a_ < 4; a_++)
#pragma unroll
        for (int b_ = 0; b_ < 4; b_++)
#pragma unroll
            for (int c_ = 0; c_ < 4; c_++) acc[a_][b_][c_] = 0.f;

    const int KT = kLen >> 5;
    uint4 ra[2], rb[2];

    // prologue: LDG tile 0, STS into buf 0
#pragma unroll
    for (int i = 0; i < 2; i++) {
        ra[i] = *(const uint4*)&A [(size_t)(m0 + rowi[i]) * lda + cci[i]];
        rb[i] = *(const uint4*)&BT[(size_t)(n0 + rowi[i]) * ldb + cci[i]];
    }
#pragma unroll
    for (int i = 0; i < 2; i++) {
        *(uint4*)&sm[rowi[i] * LDH + cci[i]]          = ra[i];
        *(uint4*)&sm[SMH_OP + rowi[i] * LDH + cci[i]] = rb[i];
    }
    __syncthreads();

    for (int kt = 0; kt < KT; kt++) {
        const int buf = kt & 1;

        // LDG next tile (overlaps MMA)
        if (kt + 1 < KT) {
            const int kb = (kt + 1) * 32;
#pragma unroll
            for (int i = 0; i < 2; i++) {
                ra[i] = *(const uint4*)&A [(size_t)(m0 + rowi[i]) * lda + kb + cci[i]];
                rb[i] = *(const uint4*)&BT[(size_t)(n0 + rowi[i]) * ldb + kb + cci[i]];
            }
        }

        // compute on buf
        const uint32_t aBuf = sbase + buf * BUFBYTES;
        const uint32_t bBuf = aBuf + OPBYTES;
#pragma unroll
        for (int kq = 0; kq < 2; kq++) {
            uint32_t bf[4][2];
#pragma unroll
            for (int nt = 0; nt < 4; nt++)
                ldsm_x2(bf[nt], bBuf + (uint32_t)(((wn * 32 + nt * 8 + rB) * LDH + kq * 16 + cB) * 2));
            uint32_t af[4][4];
#pragma unroll
            for (int mt = 0; mt < 4; mt++)
                ldsm_x4(af[mt], aBuf + (uint32_t)(((wm * 64 + mt * 16 + rA) * LDH + kq * 16 + cA) * 2));
#pragma unroll
            for (int mt = 0; mt < 4; mt++)
#pragma unroll
                for (int nt = 0; nt < 4; nt++)
                    mma_f16(acc[mt][nt], af[mt], bf[nt]);
        }

        // STS next tile into buf^1 (that buffer's consumers finished last iter)
        if (kt + 1 < KT) {
            const int o = (buf ^ 1) * 2 * SMH_OP;
#pragma unroll
            for (int i = 0; i < 2; i++) {
                *(uint4*)&sm[o + rowi[i] * LDH + cci[i]]          = ra[i];
                *(uint4*)&sm[o + SMH_OP + rowi[i] * LDH + cci[i]] = rb[i];
            }
        }
        __syncthreads();
    }

    // epilogue
#pragma unroll
    for (int mt = 0; mt < 4; mt++) {
        const int row = m0 + wm * 64 + mt * 16 + g;
#pragma unroll
        for (int nt = 0; nt < 4; nt++) {
            const int col = n0 + wn * 32 + nt * 8 + tq * 2;
            float bx = 0.f, by = 0.f;
            if (MODE < 2) { float2 bb = *(const float2*)&bias[col]; bx = bb.x; by = bb.y; }
            float v0 = acc[mt][nt][0] + bx;
            float v1 = acc[mt][nt][1] + by;
            float v2 = acc[mt][nt][2] + bx;
            float v3 = acc[mt][nt][3] + by;
            if (MODE == 1) {
                v0 = fmaxf(v0, 0.f); v1 = fmaxf(v1, 0.f);
                v2 = fmaxf(v2, 0.f); v3 = fmaxf(v3, 0.f);
            }
            if constexpr (sizeof(OutT) == 2) {
                *(__half2*)&C[(size_t)row * ldc + col]       = __floats2half2_rn(v0, v1);
                *(__half2*)&C[(size_t)(row + 8) * ldc + col] = __floats2half2_rn(v2, v3);
            } else {
                *(float2*)&C[(size_t)row * ldc + col]       = make_float2(v0, v1);
                *(float2*)&C[(size_t)(row + 8) * ldc + col] = make_float2(v2, v3);
            }
        }
    }
}

// ---------------- deformable sampling + fused softmax ------------------
// warp = (query, head); lane = (tap t=lane>>3, channel-quad c4=lane&7).
// One LDG.128 per (point, lane); cross-tap reduce via shfl_xor.
__global__ __launch_bounds__(256)
void sample_kernel(const float* __restrict__ value,
                   const float* __restrict__ offb,
                   const float* __restrict__ attnb,
                   __half* __restrict__ samp)
{
    const int m    = blockIdx.x;
    const int h    = threadIdx.x >> 5;
    const int lane = threadIdx.x & 31;
    const int b    = m / LEN_TOK;
    const int qi   = m - b * LEN_TOK;

    int Wq, idx;
    if      (qi < 4096) { Wq = 64; idx = qi; }
    else if (qi < 5120) { Wq = 32; idx = qi - 4096; }
    else if (qi < 5376) { Wq = 16; idx = qi - 5120; }
    else                { Wq = 8;  idx = qi - 5376; }
    const int   row = idx / Wq;
    const int   col = idx - row * Wq;
    const float rx  = (col + 0.5f) / (float)Wq;
    const float ry  = (row + 0.5f) / (float)Wq;

    // lane i holds offset element i (16 (x,y) pairs)
    const float offv = offb[(size_t)m * 256 + h * 32 + lane];

    // softmax over 16 logits (lanes 0..15)
    float logit = (lane < 16) ? attnb[(size_t)m * 128 + h * 16 + lane] : -1e30f;
    float mx = logit;
#pragma unroll
    for (int s = 8; s > 0; s >>= 1) mx = fmaxf(mx, __shfl_xor_sync(0xffffffffu, mx, s));
    float e = (lane < 16) ? expf(logit - mx) : 0.0f;
    float sm = e;
#pragma unroll
    for (int s = 8; s > 0; s >>= 1) sm += __shfl_xor_sync(0xffffffffu, sm, s);
    const float prob = e / sm;

    const int tap  = lane >> 3;      // 0..3
    const int c4   = lane & 7;       // channel quad
    const int xoff = tap & 1, yoff = tap >> 1;

    float4 acc = make_float4(0.f, 0.f, 0.f, 0.f);
#pragma unroll
    for (int l = 0; l < 4; l++) {
        const int   Wl = c_lvlW[l];
        const float Wf = (float)Wl;
        const float* vbase = value + ((size_t)b * LEN_TOK + c_lvlStart[l]) * 256 + h * 32 + c4 * 4;
#pragma unroll
        for (int p = 0; p < 4; p++) {
            const int j = l * 4 + p;
            const float a  = __shfl_sync(0xffffffffu, prob, j);
            const float ox = __shfl_sync(0xffffffffu, offv, 2 * j);
            const float oy = __shfl_sync(0xffffffffu, offv, 2 * j + 1);
            const float x = rx * Wf + ox - 0.5f;
            const float y = ry * Wf + oy - 0.5f;
            const float x0f = floorf(x), y0f = floorf(y);
            const float dx = x - x0f, dy = y - y0f;
            const int xi = (int)x0f + xoff;
            const int yi = (int)y0f + yoff;
            const float w = (xoff ? dx : 1.f - dx) * (yoff ? dy : 1.f - dy) * a;
            if ((xi >= 0) & (xi < Wl) & (yi >= 0) & (yi < Wl)) {
                const float4 v = *(const float4*)&vbase[(size_t)(yi * Wl + xi) * 256];
                acc.x = fmaf(w, v.x, acc.x);
                acc.y = fmaf(w, v.y, acc.y);
                acc.z = fmaf(w, v.z, acc.z);
                acc.w = fmaf(w, v.w, acc.w);
            }
        }
    }
    // reduce across the 4 taps (lanes c4, c4+8, c4+16, c4+24)
#pragma unroll
    for (int s = 8; s <= 16; s <<= 1) {
        acc.x += __shfl_xor_sync(0xffffffffu, acc.x, s);
        acc.y += __shfl_xor_sync(0xffffffffu, acc.y, s);
        acc.z += __shfl_xor_sync(0xffffffffu, acc.z, s);
        acc.w += __shfl_xor_sync(0xffffffffu, acc.w, s);
    }
    if (lane < 8) {
        __half* dst = &samp[(size_t)m * 256 + h * 32 + c4 * 4];
        *(__half2*)&dst[0] = __floats2half2_rn(acc.x, acc.y);
        *(__half2*)&dst[2] = __floats2half2_rn(acc.z, acc.w);
    }
}

// ---------------- fused residual-add + LayerNorm (fp32 + fp16 out) ------
__global__ __launch_bounds__(256)
void add_ln_kernel(const float* __restrict__ A, const float* __restrict__ Bv,
                   const float* __restrict__ gamma, const float* __restrict__ beta,
                   float* __restrict__ out, __half* __restrict__ outh)
{
    const int m = blockIdx.x;
    const int t = threadIdx.x;
    const float v = A[(size_t)m * 256 + t] + Bv[(size_t)m * 256 + t];

    float s = v, q2 = v * v;
#pragma unroll
    for (int sft = 16; sft > 0; sft >>= 1) {
        s  += __shfl_xor_sync(0xffffffffu, s,  sft);
        q2 += __shfl_xor_sync(0xffffffffu, q2, sft);
    }
    __shared__ float ws[8], wq[8], mv[2];
    const int wid = t >> 5, lane = t & 31;
    if (lane == 0) { ws[wid] = s; wq[wid] = q2; }
    __syncthreads();
    if (t == 0) {
        float ts = 0.f, tq_ = 0.f;
#pragma unroll
        for (int i = 0; i < 8; i++) { ts += ws[i]; tq_ += wq[i]; }
        const float mean = ts * (1.0f / 256.0f);
        const float var  = tq_ * (1.0f / 256.0f) - mean * mean;
        mv[0] = mean;
        mv[1] = rsqrtf(var + 1e-5f);
    }
    __syncthreads();
    const float o = (v - mv[0]) * mv[1] * gamma[t] + beta[t];
    out[(size_t)m * 256 + t]  = o;
    outh[(size_t)m * 256 + t] = __float2half_rn(o);
}

// ---- fused: 4 split-K partials + bias + residual + LayerNorm -----------
__global__ __launch_bounds__(256)
void add4_ln_kernel(const float* __restrict__ X, const float* __restrict__ P,
                    const float* __restrict__ bias,
                    const float* __restrict__ gamma, const float* __restrict__ beta,
                    float* __restrict__ out)
{
    const int m = blockIdx.x;
    const int t = threadIdx.x;
    const size_t i = (size_t)m * 256 + t;
    const size_t sl = (size_t)M_TOK * 256;
    const float v = X[i] + P[i] + P[i + sl] + P[i + 2 * sl] + P[i + 3 * sl] + bias[t];

    float s = v, q2 = v * v;
#pragma unroll
    for (int sft = 16; sft > 0; sft >>= 1) {
        s  += __shfl_xor_sync(0xffffffffu, s,  sft);
        q2 += __shfl_xor_sync(0xffffffffu, q2, sft);
    }
    __shared__ float ws[8], wq[8], mv[2];
    const int wid = t >> 5, lane = t & 31;
    if (lane == 0) { ws[wid] = s; wq[wid] = q2; }
    __syncthreads();
    if (t == 0) {
        float ts = 0.f, tq_ = 0.f;
#pragma unroll
        for (int ii = 0; ii < 8; ii++) { ts += ws[ii]; tq_ += wq[ii]; }
        const float mean = ts * (1.0f / 256.0f);
        const float var  = tq_ * (1.0f / 256.0f) - mean * mean;
        mv[0] = mean;
        mv[1] = rsqrtf(var + 1e-5f);
    }
    __syncthreads();
    out[i] = (v - mv[0]) * mv[1] * gamma[t] + beta[t];
}

// ---------------- launch -------------------------------------------------
template <typename T>
static inline T* sym(const void* s)
{
    void* p = nullptr;
    cudaGetSymbolAddress(&p, s);
    return (T*)p;
}

extern "C" void kernel_launch(void* const* d_in, const int* in_sizes, int n_in,
                              void* d_out, int out_size)
{
    const float* src     = (const float*)d_in[0];
    const float* pos     = (const float*)d_in[1];
    const float* w_value = (const float*)d_in[4];
    const float* b_value = (const float*)d_in[5];
    const float* w_off   = (const float*)d_in[6];
    const float* b_off   = (const float*)d_in[7];
    const float* w_attn  = (const float*)d_in[8];
    const float* b_attn  = (const float*)d_in[9];
    const float* w_out   = (const float*)d_in[10];
    const float* b_out   = (const float*)d_in[11];
    const float* w1      = (const float*)d_in[12];
    const float* b1      = (const float*)d_in[13];
    const float* w2      = (const float*)d_in[14];
    const float* b2      = (const float*)d_in[15];
    const float* g1      = (const float*)d_in[16];
    const float* be1     = (const float*)d_in[17];
    const float* g2      = (const float*)d_in[18];
    const float* be2     = (const float*)d_in[19];
    float* out = (float*)d_out;

    float*  val   = sym<float>(g_val);
    float*  off   = sym<float>(g_off);
    float*  attn  = sym<float>(g_attn);
    float*  out2  = sym<float>(g_out2);
    float*  x     = sym<float>(g_x);
    float*  part  = sym<float>(g_part);
    __half* srch  = sym<__half>(g_srch);
    __half* qh    = sym<__half>(g_qh);
    __half* samph = sym<__half>(g_samph);
    __half* xh    = sym<__half>(g_xh);
    __half* ffhh  = sym<__half>(g_ffhh);
    __half* wvT    = sym<__half>(g_wvT);
    __half* woffT  = sym<__half>(g_woffT);
    __half* wattnT = sym<__half>(g_wattnT);
    __half* woutT  = sym<__half>(g_woutT);
    __half* w1T    = sym<__half>(g_w1T);
    __half* w2T    = sym<__half>(g_w2T);

    const int n4 = M_TOK * DMODEL / 4;

    // q = src + pos (fp16) and src -> fp16, one launch
    addcvt_kernel<<<(n4 + 255) / 256, 256>>>((const float4*)src, (const float4*)pos,
                                             (__half2*)qh, (__half2*)srch, n4);

    // all weight transposes + fp16 convert, one launch
    transpose_all<<<1248, dim3(32, 8)>>>(w_value, w_off, w_attn, w_out, w1, w2,
                                         wvT, woffT, wattnT, woutT, w1T, w2T);

    // projections (fp16 mma.sync, fp32 out)
    dim3 gv(2, M_TOK / 128, 1);
    gemm_mma<0, float><<<gv, 256>>>(srch, 256, wvT,    256, val,  256, 0, b_value, 256);
    gemm_mma<0, float><<<gv, 256>>>(qh,   256, woffT,  256, off,  256, 0, b_off,   256);
    dim3 ga(1, M_TOK / 128, 1);
    gemm_mma<0, float><<<ga, 256>>>(qh,   256, wattnT, 256, attn, 128, 0, b_attn,  256);

    // deformable sampling (softmax fused), fp16 output
    sample_kernel<<<M_TOK, 256>>>(val, off, attn, samph);

    // output projection
    gemm_mma<0, float><<<gv, 256>>>(samph, 256, woutT, 256, out2, 256, 0, b_out, 256);

    // x = LN(src + out2), fp32 + fp16
    add_ln_kernel<<<M_TOK, 256>>>(src, out2, g1, be1, x, xh);

    // FFN1: relu(x @ w1 + b1), fp16 out
    dim3 gf1(DFF / 128, M_TOK / 128, 1);
    gemm_mma<1, __half><<<gf1, 256>>>(xh, 256, w1T, 256, ffhh, DFF, 0, b1, 256);

    // FFN2: split-K=4 partials (kLen=512 each)
    dim3 gf2(2, M_TOK / 128, 4);
    gemm_mma<2, float><<<gf2, 256>>>(ffhh, DFF, w2T, DFF, part, 256,
                                     (size_t)M_TOK * 256, nullptr, 512);

    // out = LN(x + sum(parts) + b2)
    add4_ln_kernel<<<M_TOK, 256>>>(x, part, b2, g2, be2, out);
}

// round 5
// speedup vs baseline: 3.6772x; 1.0479x over previous
#include <cuda_runtime.h>
#include <cuda_fp16.h>
#include <cstdint>
#include <math.h>

// ---------------- problem constants (fixed by dataset) ----------------
#define B_BATCH   2
#define LEN_TOK   5440
#define M_TOK     (B_BATCH * LEN_TOK)   // 10880
#define DMODEL    256
#define NHEAD     8
#define NLVL      4
#define NPT       4
#define DFF       2048

__device__ __constant__ int c_lvlW[4]     = {64, 32, 16, 8};
__device__ __constant__ int c_lvlStart[4] = {0, 4096, 5120, 5376};

// ---------------- scratch (static device globals; no allocation) ------
__device__ __half g_valh[M_TOK * DMODEL];
__device__ float  g_offattn[M_TOK * 384];       // cols 0..255 off, 256..383 attn
__device__ float  g_out2[M_TOK * DMODEL];
__device__ float  g_x   [M_TOK * DMODEL];
__device__ float  g_part[4 * M_TOK * DMODEL];   // split-K partials for FFN2
__device__ __half g_srch[M_TOK * DMODEL];
__device__ __half g_qh  [M_TOK * DMODEL];
__device__ __half g_samph[M_TOK * DMODEL];
__device__ __half g_xh  [M_TOK * DMODEL];
__device__ __half g_ffhh[M_TOK * DFF];
__device__ float  g_boa [384];                  // concat(b_off, b_attn)
// transposed fp16 weights [N, K]
__device__ __half g_wvT  [256 * 256];
__device__ __half g_woaT [384 * 256];           // rows 0..255 off, 256..383 attn
__device__ __half g_woutT[256 * 256];
__device__ __half g_w1T  [2048 * 256];
__device__ __half g_w2T  [256 * 2048];

// ---------------- mma / ldmatrix / cp.async helpers ----------------------
__device__ __forceinline__ void mma_f16(float* c, const uint32_t* a, const uint32_t* b) {
    asm volatile(
        "mma.sync.aligned.m16n8k16.row.col.f32.f16.f16.f32 "
        "{%0,%1,%2,%3}, {%4,%5,%6,%7}, {%8,%9}, {%0,%1,%2,%3};\n"
        : "+f"(c[0]), "+f"(c[1]), "+f"(c[2]), "+f"(c[3])
        : "r"(a[0]), "r"(a[1]), "r"(a[2]), "r"(a[3]), "r"(b[0]), "r"(b[1]));
}
__device__ __forceinline__ void ldsm_x4(uint32_t* r, uint32_t addr) {
    asm volatile("ldmatrix.sync.aligned.m8n8.x4.shared.b16 {%0,%1,%2,%3}, [%4];"
                 : "=r"(r[0]), "=r"(r[1]), "=r"(r[2]), "=r"(r[3]) : "r"(addr));
}
__device__ __forceinline__ void ldsm_x2(uint32_t* r, uint32_t addr) {
    asm volatile("ldmatrix.sync.aligned.m8n8.x2.shared.b16 {%0,%1}, [%2];"
                 : "=r"(r[0]), "=r"(r[1]) : "r"(addr));
}
__device__ __forceinline__ void cp16(uint32_t saddr, const void* g) {
    asm volatile("cp.async.cg.shared.global [%0], [%1], 16;" :: "r"(saddr), "l"(g));
}
#define CP_COMMIT() asm volatile("cp.async.commit_group;" ::: "memory")
#define CP_WAIT1()  asm volatile("cp.async.wait_group 1;" ::: "memory")

// ---------------- q = src + pos (fp16 copies of both) --------------------
__global__ void addcvt_kernel(const float4* __restrict__ src, const float4* __restrict__ pos,
                              __half2* __restrict__ qh, __half2* __restrict__ srch, int n4)
{
    int i = blockIdx.x * blockDim.x + threadIdx.x;
    if (i < n4) {
        float4 s = src[i], p = pos[i];
        srch[2 * i]     = __floats2half2_rn(s.x, s.y);
        srch[2 * i + 1] = __floats2half2_rn(s.z, s.w);
        qh[2 * i]       = __floats2half2_rn(s.x + p.x, s.y + p.y);
        qh[2 * i + 1]   = __floats2half2_rn(s.z + p.z, s.w + p.w);
    }
}

// ---------------- all weight transposes (fp32 [K,N] -> fp16 [N,K]) -------
__global__ __launch_bounds__(256)
void transpose_all(const float* __restrict__ wv, const float* __restrict__ woff,
                   const float* __restrict__ wattn, const float* __restrict__ wout,
                   const float* __restrict__ w1, const float* __restrict__ w2,
                   __half* __restrict__ wvT, __half* __restrict__ woaT,
                   __half* __restrict__ woutT,
                   __half* __restrict__ w1T, __half* __restrict__ w2T)
{
    const int bid = blockIdx.x;
    const float* in; __half* out; int R, C, tix;
    if      (bid < 64)  { in = wv;    out = wvT;            R = 256;  C = 256;  tix = bid; }
    else if (bid < 128) { in = woff;  out = woaT;           R = 256;  C = 256;  tix = bid - 64; }
    else if (bid < 160) { in = wattn; out = woaT + 256*256; R = 256;  C = 128;  tix = bid - 128; }
    else if (bid < 224) { in = wout;  out = woutT;          R = 256;  C = 256;  tix = bid - 160; }
    else if (bid < 736) { in = w1;    out = w1T;            R = 256;  C = 2048; tix = bid - 224; }
    else                { in = w2;    out = w2T;            R = 2048; C = 256;  tix = bid - 736; }
    const int tilesX = C / 32;
    const int c0 = (tix % tilesX) * 32, r0 = (tix / tilesX) * 32;

    __shared__ float tile[32][33];
    const int x = threadIdx.x, y = threadIdx.y;   // block (32, 8)
#pragma unroll
    for (int i = 0; i < 32; i += 8)
        tile[y + i][x] = in[(size_t)(r0 + y + i) * C + c0 + x];
    __syncthreads();
#pragma unroll
    for (int i = 0; i < 32; i += 8)
        out[(size_t)(c0 + y + i) * R + r0 + x] = __float2half_rn(tile[x][y + i]);
}

// ---------------- fp16 mma.sync GEMM, 3-stage cp.async pipeline ----------
// C[M,N] = A[M,kLen] @ BT[N,kLen]^T (+bias/relu per MODE)
// CTA 128x128, BK=32, 256 thr = 8 warps (2m x 4n), warp tile 64x32.
// Split-K via blockIdx.z. MODE: 0 +bias, 1 +bias+relu, 2 raw partial.
#define LDH      40
#define SMH_OP   (128 * LDH)            // halves per operand per stage
#define OPBYTES  (SMH_OP * 2)           // 10240
#define STAGEB   (2 * OPBYTES)          // 20480
#define NSTAGE   3
#define SMBYTES  (NSTAGE * STAGEB)      // 61440

template <int MODE, typename OutT>
__global__ __launch_bounds__(256, 2)
void gemm_mma(const __half* __restrict__ A, int lda,
              const __half* __restrict__ BT, int ldb,
              OutT* __restrict__ C, int ldc, size_t cSlice,
              const float* __restrict__ bias, int kLen)
{
    extern __shared__ __align__(16) __half sm[];

    const int t    = threadIdx.x;
    const int warp = t >> 5;
    const int lane = t & 31;
    const int wm   = warp >> 2;      // 0..1
    const int wn   = warp & 3;       // 0..3
    const int g    = lane >> 2;      // 0..7
    const int tq   = lane & 3;       // 0..3
    const int m0 = blockIdx.y * 128;
    const int n0 = blockIdx.x * 128;

    A  += (size_t)blockIdx.z * kLen;
    BT += (size_t)blockIdx.z * kLen;
    C  += (size_t)blockIdx.z * cSlice;

    const uint32_t sbase = (uint32_t)__cvta_generic_to_shared(sm);

    // staging geometry: 2 chunks of 16B per operand per thread
    int rowi[2], cci[2];
#pragma unroll
    for (int i = 0; i < 2; i++) {
        const int f = t + i * 256;
        rowi[i] = f >> 2;             // 0..127
        cci[i]  = (f & 3) * 8;        // halves: 0,8,16,24
    }
    // ldmatrix lane geometry
    const int rA = ((lane >> 3) & 1) * 8 + (lane & 7);
    const int cA = (lane >> 4) * 8;
    const int rB = lane & 7;
    const int cB = ((lane >> 3) & 1) * 8;

    float acc[4][4][4];
#pragma unroll
    for (int a_ = 0; a_ < 4; a_++)
#pragma unroll
        for (int b_ = 0; b_ < 4; b_++)
#pragma unroll
            for (int c_ = 0; c_ < 4; c_++) acc[a_][b_][c_] = 0.f;

    const int KT = kLen >> 5;   // >= 8 for all calls

    // prologue: issue stages 0 and 1
#pragma unroll
    for (int s = 0; s < 2; s++) {
        const int kb = s * 32;
        const uint32_t sb = sbase + s * STAGEB;
#pragma unroll
        for (int i = 0; i < 2; i++) {
            const uint32_t da = sb + (uint32_t)((rowi[i] * LDH + cci[i]) * 2);
            cp16(da,           &A [(size_t)(m0 + rowi[i]) * lda + kb + cci[i]]);
            cp16(da + OPBYTES, &BT[(size_t)(n0 + rowi[i]) * ldb + kb + cci[i]]);
        }
        CP_COMMIT();
    }

    for (int kt = 0; kt < KT; kt++) {
        CP_WAIT1();          // stage kt complete (kt+1 may stay in flight)
        __syncthreads();     // all warps: stage kt visible, compute kt-1 done

        // issue stage kt+2 into buffer (kt+2)%3 (last used at iter kt-1)
        const int nkt = kt + 2;
        if (nkt < KT) {
            const int kb = nkt * 32;
            const uint32_t sb = sbase + (nkt % NSTAGE) * STAGEB;
#pragma unroll
            for (int i = 0; i < 2; i++) {
                const uint32_t da = sb + (uint32_t)((rowi[i] * LDH + cci[i]) * 2);
                cp16(da,           &A [(size_t)(m0 + rowi[i]) * lda + kb + cci[i]]);
                cp16(da + OPBYTES, &BT[(size_t)(n0 + rowi[i]) * ldb + kb + cci[i]]);
            }
        }
        CP_COMMIT();         // always commit (keeps group accounting uniform)

        // compute on stage kt
        const uint32_t aBuf = sbase + (kt % NSTAGE) * STAGEB;
        const uint32_t bBuf = aBuf + OPBYTES;
#pragma unroll
        for (int kq = 0; kq < 2; kq++) {
            uint32_t bf[4][2];
#pragma unroll
            for (int nt = 0; nt < 4; nt++)
                ldsm_x2(bf[nt], bBuf + (uint32_t)(((wn * 32 + nt * 8 + rB) * LDH + kq * 16 + cB) * 2));
            uint32_t af[4][4];
#pragma unroll
            for (int mt = 0; mt < 4; mt++)
                ldsm_x4(af[mt], aBuf + (uint32_t)(((wm * 64 + mt * 16 + rA) * LDH + kq * 16 + cA) * 2));
#pragma unroll
            for (int mt = 0; mt < 4; mt++)
#pragma unroll
                for (int nt = 0; nt < 4; nt++)
                    mma_f16(acc[mt][nt], af[mt], bf[nt]);
        }
    }

    // epilogue
#pragma unroll
    for (int mt = 0; mt < 4; mt++) {
        const int row = m0 + wm * 64 + mt * 16 + g;
#pragma unroll
        for (int nt = 0; nt < 4; nt++) {
            const int col = n0 + wn * 32 + nt * 8 + tq * 2;
            float bx = 0.f, by = 0.f;
            if (MODE < 2) { float2 bb = *(const float2*)&bias[col]; bx = bb.x; by = bb.y; }
            float v0 = acc[mt][nt][0] + bx;
            float v1 = acc[mt][nt][1] + by;
            float v2 = acc[mt][nt][2] + bx;
            float v3 = acc[mt][nt][3] + by;
            if (MODE == 1) {
                v0 = fmaxf(v0, 0.f); v1 = fmaxf(v1, 0.f);
                v2 = fmaxf(v2, 0.f); v3 = fmaxf(v3, 0.f);
            }
            if constexpr (sizeof(OutT) == 2) {
                *(__half2*)&C[(size_t)row * ldc + col]       = __floats2half2_rn(v0, v1);
                *(__half2*)&C[(size_t)(row + 8) * ldc + col] = __floats2half2_rn(v2, v3);
            } else {
                *(float2*)&C[(size_t)row * ldc + col]       = make_float2(v0, v1);
                *(float2*)&C[(size_t)(row + 8) * ldc + col] = make_float2(v2, v3);
            }
        }
    }
}

// ---------------- deformable sampling + fused softmax ------------------
// warp = (query, head); lane = (tap, channel-quad); fp16 value gather.
__global__ __launch_bounds__(256)
void sample_kernel(const __half* __restrict__ value,
                   const float* __restrict__ oa,      // [M,384] off|attn
                   __half* __restrict__ samp)
{
    const int m    = blockIdx.x;
    const int h    = threadIdx.x >> 5;
    const int lane = threadIdx.x & 31;
    const int b    = m / LEN_TOK;
    const int qi   = m - b * LEN_TOK;

    int Wq, idx;
    if      (qi < 4096) { Wq = 64; idx = qi; }
    else if (qi < 5120) { Wq = 32; idx = qi - 4096; }
    else if (qi < 5376) { Wq = 16; idx = qi - 5120; }
    else                { Wq = 8;  idx = qi - 5376; }
    const int   row = idx / Wq;
    const int   col = idx - row * Wq;
    const float rx  = (col + 0.5f) / (float)Wq;
    const float ry  = (row + 0.5f) / (float)Wq;

    // lane i holds offset element i (16 (x,y) pairs)
    const float offv = oa[(size_t)m * 384 + h * 32 + lane];

    // softmax over 16 logits (lanes 0..15)
    float logit = (lane < 16) ? oa[(size_t)m * 384 + 256 + h * 16 + lane] : -1e30f;
    float mx = logit;
#pragma unroll
    for (int s = 8; s > 0; s >>= 1) mx = fmaxf(mx, __shfl_xor_sync(0xffffffffu, mx, s));
    float e = (lane < 16) ? expf(logit - mx) : 0.0f;
    float sm = e;
#pragma unroll
    for (int s = 8; s > 0; s >>= 1) sm += __shfl_xor_sync(0xffffffffu, sm, s);
    const float prob = e / sm;

    const int tap  = lane >> 3;      // 0..3
    const int c4   = lane & 7;       // channel quad
    const int xoff = tap & 1, yoff = tap >> 1;

    float4 acc = make_float4(0.f, 0.f, 0.f, 0.f);
#pragma unroll
    for (int l = 0; l < 4; l++) {
        const int   Wl = c_lvlW[l];
        const float Wf = (float)Wl;
        const __half* vbase = value + ((size_t)b * LEN_TOK + c_lvlStart[l]) * 256 + h * 32 + c4 * 4;
#pragma unroll
        for (int p = 0; p < 4; p++) {
            const int j = l * 4 + p;
            const float a  = __shfl_sync(0xffffffffu, prob, j);
            const float ox = __shfl_sync(0xffffffffu, offv, 2 * j);
            const float oy = __shfl_sync(0xffffffffu, offv, 2 * j + 1);
            const float x = rx * Wf + ox - 0.5f;
            const float y = ry * Wf + oy - 0.5f;
            const float x0f = floorf(x), y0f = floorf(y);
            const float dx = x - x0f, dy = y - y0f;
            const int xi = (int)x0f + xoff;
            const int yi = (int)y0f + yoff;
            const float w = (xoff ? dx : 1.f - dx) * (yoff ? dy : 1.f - dy) * a;
            if ((xi >= 0) & (xi < Wl) & (yi >= 0) & (yi < Wl)) {
                const uint2 raw = *(const uint2*)&vbase[(size_t)(yi * Wl + xi) * 256];
                const float2 v01 = __half22float2(*(const __half2*)&raw.x);
                const float2 v23 = __half22float2(*(const __half2*)&raw.y);
                acc.x = fmaf(w, v01.x, acc.x);
                acc.y = fmaf(w, v01.y, acc.y);
                acc.z = fmaf(w, v23.x, acc.z);
                acc.w = fmaf(w, v23.y, acc.w);
            }
        }
    }
    // reduce across the 4 taps
#pragma unroll
    for (int s = 8; s <= 16; s <<= 1) {
        acc.x += __shfl_xor_sync(0xffffffffu, acc.x, s);
        acc.y += __shfl_xor_sync(0xffffffffu, acc.y, s);
        acc.z += __shfl_xor_sync(0xffffffffu, acc.z, s);
        acc.w += __shfl_xor_sync(0xffffffffu, acc.w, s);
    }
    if (lane < 8) {
        __half* dst = &samp[(size_t)m * 256 + h * 32 + c4 * 4];
        *(__half2*)&dst[0] = __floats2half2_rn(acc.x, acc.y);
        *(__half2*)&dst[2] = __floats2half2_rn(acc.z, acc.w);
    }
}

// ---------------- fused residual-add + LayerNorm (fp32 + fp16 out) ------
__global__ __launch_bounds__(256)
void add_ln_kernel(const float* __restrict__ A, const float* __restrict__ Bv,
                   const float* __restrict__ gamma, const float* __restrict__ beta,
                   float* __restrict__ out, __half* __restrict__ outh)
{
    const int m = blockIdx.x;
    const int t = threadIdx.x;
    const float v = A[(size_t)m * 256 + t] + Bv[(size_t)m * 256 + t];

    float s = v, q2 = v * v;
#pragma unroll
    for (int sft = 16; sft > 0; sft >>= 1) {
        s  += __shfl_xor_sync(0xffffffffu, s,  sft);
        q2 += __shfl_xor_sync(0xffffffffu, q2, sft);
    }
    __shared__ float ws[8], wq[8], mv[2];
    const int wid = t >> 5, lane = t & 31;
    if (lane == 0) { ws[wid] = s; wq[wid] = q2; }
    __syncthreads();
    if (t == 0) {
        float ts = 0.f, tq_ = 0.f;
#pragma unroll
        for (int i = 0; i < 8; i++) { ts += ws[i]; tq_ += wq[i]; }
        const float mean = ts * (1.0f / 256.0f);
        const float var  = tq_ * (1.0f / 256.0f) - mean * mean;
        mv[0] = mean;
        mv[1] = rsqrtf(var + 1e-5f);
    }
    __syncthreads();
    const float o = (v - mv[0]) * mv[1] * gamma[t] + beta[t];
    out[(size_t)m * 256 + t]  = o;
    outh[(size_t)m * 256 + t] = __float2half_rn(o);
}

// ---- fused: 4 split-K partials + bias + residual + LayerNorm -----------
__global__ __launch_bounds__(256)
void add4_ln_kernel(const float* __restrict__ X, const float* __restrict__ P,
                    const float* __restrict__ bias,
                    const float* __restrict__ gamma, const float* __restrict__ beta,
                    float* __restrict__ out)
{
    const int m = blockIdx.x;
    const int t = threadIdx.x;
    const size_t i = (size_t)m * 256 + t;
    const size_t sl = (size_t)M_TOK * 256;
    const float v = X[i] + P[i] + P[i + sl] + P[i + 2 * sl] + P[i + 3 * sl] + bias[t];

    float s = v, q2 = v * v;
#pragma unroll
    for (int sft = 16; sft > 0; sft >>= 1) {
        s  += __shfl_xor_sync(0xffffffffu, s,  sft);
        q2 += __shfl_xor_sync(0xffffffffu, q2, sft);
    }
    __shared__ float ws[8], wq[8], mv[2];
    const int wid = t >> 5, lane = t & 31;
    if (lane == 0) { ws[wid] = s; wq[wid] = q2; }
    __syncthreads();
    if (t == 0) {
        float ts = 0.f, tq_ = 0.f;
#pragma unroll
        for (int ii = 0; ii < 8; ii++) { ts += ws[ii]; tq_ += wq[ii]; }
        const float mean = ts * (1.0f / 256.0f);
        const float var  = tq_ * (1.0f / 256.0f) - mean * mean;
        mv[0] = mean;
        mv[1] = rsqrtf(var + 1e-5f);
    }
    __syncthreads();
    out[i] = (v - mv[0]) * mv[1] * gamma[t] + beta[t];
}

// ---------------- launch -------------------------------------------------
template <typename T>
static inline T* sym(const void* s)
{
    void* p = nullptr;
    cudaGetSymbolAddress(&p, s);
    return (T*)p;
}

extern "C" void kernel_launch(void* const* d_in, const int* in_sizes, int n_in,
                              void* d_out, int out_size)
{
    const float* src     = (const float*)d_in[0];
    const float* pos     = (const float*)d_in[1];
    const float* w_value = (const float*)d_in[4];
    const float* b_value = (const float*)d_in[5];
    const float* w_off   = (const float*)d_in[6];
    const float* b_off   = (const float*)d_in[7];
    const float* w_attn  = (const float*)d_in[8];
    const float* b_attn  = (const float*)d_in[9];
    const float* w_out   = (const float*)d_in[10];
    const float* b_out   = (const float*)d_in[11];
    const float* w1      = (const float*)d_in[12];
    const float* b1      = (const float*)d_in[13];
    const float* w2      = (const float*)d_in[14];
    const float* b2      = (const float*)d_in[15];
    const float* g1      = (const float*)d_in[16];
    const float* be1     = (const float*)d_in[17];
    const float* g2      = (const float*)d_in[18];
    const float* be2     = (const float*)d_in[19];
    float* out = (float*)d_out;

    __half* valh    = sym<__half>(g_valh);
    float*  offattn = sym<float>(g_offattn);
    float*  out2    = sym<float>(g_out2);
    float*  x       = sym<float>(g_x);
    float*  part    = sym<float>(g_part);
    float*  boa     = sym<float>(g_boa);
    __half* srch    = sym<__half>(g_srch);
    __half* qh      = sym<__half>(g_qh);
    __half* samph   = sym<__half>(g_samph);
    __half* xh      = sym<__half>(g_xh);
    __half* ffhh    = sym<__half>(g_ffhh);
    __half* wvT     = sym<__half>(g_wvT);
    __half* woaT    = sym<__half>(g_woaT);
    __half* woutT   = sym<__half>(g_woutT);
    __half* w1T     = sym<__half>(g_w1T);
    __half* w2T     = sym<__half>(g_w2T);

    // dynamic smem opt-in (idempotent host-side attribute set)
    cudaFuncSetAttribute(gemm_mma<0, float>,  cudaFuncAttributeMaxDynamicSharedMemorySize, SMBYTES);
    cudaFuncSetAttribute(gemm_mma<0, __half>, cudaFuncAttributeMaxDynamicSharedMemorySize, SMBYTES);
    cudaFuncSetAttribute(gemm_mma<1, __half>, cudaFuncAttributeMaxDynamicSharedMemorySize, SMBYTES);
    cudaFuncSetAttribute(gemm_mma<2, float>,  cudaFuncAttributeMaxDynamicSharedMemorySize, SMBYTES);

    const int n4 = M_TOK * DMODEL / 4;

    // q = src + pos (fp16) and src -> fp16
    addcvt_kernel<<<(n4 + 255) / 256, 256>>>((const float4*)src, (const float4*)pos,
                                             (__half2*)qh, (__half2*)srch, n4);

    // weight transposes + fp16 convert (one launch) + concat biases
    transpose_all<<<1248, dim3(32, 8)>>>(w_value, w_off, w_attn, w_out, w1, w2,
                                         wvT, woaT, woutT, w1T, w2T);
    cudaMemcpyAsync(boa,       b_off,  256 * sizeof(float), cudaMemcpyDeviceToDevice);
    cudaMemcpyAsync(boa + 256, b_attn, 128 * sizeof(float), cudaMemcpyDeviceToDevice);

    // value projection -> fp16
    dim3 gv(2, M_TOK / 128, 1);
    gemm_mma<0, __half><<<gv, 256, SMBYTES>>>(srch, 256, wvT, 256, valh, 256, 0, b_value, 256);

    // fused off+attn projection (N=384)
    dim3 go(3, M_TOK / 128, 1);
    gemm_mma<0, float><<<go, 256, SMBYTES>>>(qh, 256, woaT, 256, offattn, 384, 0, boa, 256);

    // deformable sampling (softmax fused), fp16 in/out
    sample_kernel<<<M_TOK, 256>>>(valh, offattn, samph);

    // output projection
    gemm_mma<0, float><<<gv, 256, SMBYTES>>>(samph, 256, woutT, 256, out2, 256, 0, b_out, 256);

    // x = LN(src + out2), fp32 + fp16
    add_ln_kernel<<<M_TOK, 256>>>(src, out2, g1, be1, x, xh);

    // FFN1: relu(x @ w1 + b1), fp16 out
    dim3 gf1(DFF / 128, M_TOK / 128, 1);
    gemm_mma<1, __half><<<gf1, 256, SMBYTES>>>(xh, 256, w1T, 256, ffhh, DFF, 0, b1, 256);

    // FFN2: split-K=4 partials (kLen=512 each)
    dim3 gf2(2, M_TOK / 128, 4);
    gemm_mma<2, float><<<gf2, 256, SMBYTES>>>(ffhh, DFF, w2T, DFF, part, 256,
                                              (size_t)M_TOK * 256, nullptr, 512);

    // out = LN(x + sum(parts) + b2)
    add4_ln_kernel<<<M_TOK, 256>>>(x, part, b2, g2, be2, out);
}